// round 1
// baseline (speedup 1.0000x reference)
#include <cuda_runtime.h>

#define B    512
#define L    32768
#define WSZ  100                 // WINDOW*3 - 2
#define NOUT (L - WSZ + 1)       // 32669
#define TPB  128
#define KPT  32
#define CHUNK (TPB * KPT)        // 4096 outputs per block
#define STAGE (CHUNK + WSZ - 1)  // 4195 staged inputs
#define RGROUPS 8
#define ROWS_PER_G (B / RGROUPS) // 64

// Scratch (static device arrays — no allocation in kernel_launch)
__device__ float g_corr[(size_t)B * NOUT];
__device__ float g_partial[RGROUPS * NOUT];
__device__ float g_avg[NOUT];

// K1: per-row windowed correlation, exact sliding sums.
__global__ __launch_bounds__(TPB) void corr_kernel(const float* __restrict__ x) {
    __shared__ float sa[STAGE];
    __shared__ float sb[STAGE];
    const int row = blockIdx.y;
    const int c0  = blockIdx.x * CHUNK;
    const float* __restrict__ x1 = x + (size_t)row * (2 * L);
    const float* __restrict__ x2 = x1 + L;

    for (int i = threadIdx.x; i < STAGE; i += TPB) {
        int idx = c0 + i;
        float a = 0.f, b = 0.f;
        if (idx < L) { a = x1[idx]; b = x2[idx]; }
        sa[i] = a; sb[i] = b;
    }
    __syncthreads();

    const int base = threadIdx.x * KPT;
    float s1 = 0.f, s2 = 0.f, s11 = 0.f, s22 = 0.f, s12 = 0.f;
    #pragma unroll 5
    for (int i = 0; i < WSZ; i++) {
        float a = sa[base + i], b = sb[base + i];
        s1 += a; s2 += b; s11 += a * a; s22 += b * b; s12 += a * b;
    }

    const float invw = 1.0f / (float)WSZ;
    float* __restrict__ orow = g_corr + (size_t)row * NOUT;
    #pragma unroll
    for (int k = 0; k < KPT; k++) {
        int j = c0 + base + k;
        if (j < NOUT) {
            float cov = s12 - s1 * s2 * invw;
            float v1  = s11 - s1 * s1 * invw;
            float v2  = s22 - s2 * s2 * invw;
            orow[j] = cov * rsqrtf(v1 * v2);
        }
        if (k + 1 < KPT) {
            float an = sa[base + WSZ + k], bn = sb[base + WSZ + k];
            float ao = sa[base + k],       bo = sb[base + k];
            s1  += an - ao;
            s2  += bn - bo;
            s11 += an * an - ao * ao;
            s22 += bn * bn - bo * bo;
            s12 += an * bn - ao * bo;
        }
    }
}

// K2: partial column sums over 64-row groups (coalesced across columns).
__global__ __launch_bounds__(256) void colsum_kernel() {
    int c = blockIdx.x * blockDim.x + threadIdx.x;
    int g = blockIdx.y;
    if (c >= NOUT) return;
    const float* __restrict__ p = g_corr + (size_t)g * ROWS_PER_G * NOUT + c;
    float s = 0.f;
    #pragma unroll
    for (int r = 0; r < ROWS_PER_G; r++) s += p[(size_t)r * NOUT];
    g_partial[g * NOUT + c] = s;
}

// K2b: collapse partials -> avg.
__global__ __launch_bounds__(256) void avg_kernel() {
    int c = blockIdx.x * blockDim.x + threadIdx.x;
    if (c >= NOUT) return;
    float s = 0.f;
    #pragma unroll
    for (int g = 0; g < RGROUPS; g++) s += g_partial[g * NOUT + c];
    g_avg[c] = s * (1.0f / (float)B);
}

// K3: out = relu(corr - avg)
__global__ __launch_bounds__(256) void final_kernel(float* __restrict__ out) {
    int c = blockIdx.x * blockDim.x + threadIdx.x;
    int r = blockIdx.y;
    if (c >= NOUT) return;
    size_t i = (size_t)r * NOUT + c;
    float v = g_corr[i] - g_avg[c];
    out[i] = v > 0.f ? v : 0.f;
}

extern "C" void kernel_launch(void* const* d_in, const int* in_sizes, int n_in,
                              void* d_out, int out_size) {
    const float* x = (const float*)d_in[0];
    float* out = (float*)d_out;

    dim3 g1((NOUT + CHUNK - 1) / CHUNK, B);
    corr_kernel<<<g1, TPB>>>(x);

    dim3 g2((NOUT + 255) / 256, RGROUPS);
    colsum_kernel<<<g2, 256>>>();

    avg_kernel<<<(NOUT + 255) / 256, 256>>>();

    dim3 g3((NOUT + 255) / 256, B);
    final_kernel<<<g3, 256>>>(out);
}